// round 8
// baseline (speedup 1.0000x reference)
#include <cuda_runtime.h>

// ---------------------------------------------------------------------------
// SSIM loss, fully fused single kernel: 5 separable 11x11 Gaussian convs +
// SSIM map + global mean. pred/target: (32,3,512,512) fp32.
// Output: scalar fp32 = 1 - mean(ssim_map).
// ---------------------------------------------------------------------------

namespace {
constexpr int IMG  = 512;
constexpr int TW   = 64;          // output tile width
constexpr int TH   = 48;          // output tile height
constexpr int SWH  = TW + 10;     // 74  halo width
constexpr int SHH  = TH + 10;     // 58  halo height
constexpr int SWM  = 76;          // padded mid-row stride (16B aligned)
constexpr int NT   = 256;         // threads per block
constexpr int VY   = 8;           // rows per thread in vertical pass
constexpr int HX   = 4;           // cols per thread in horizontal pass
constexpr int HALO_ELEMS = SHH * SWH;              // 4292
constexpr int MID_ELEMS  = TH * SWM;               // 3648
constexpr int SMEM_FLOATS = 2 * HALO_ELEMS + 5 * MID_ELEMS;  // 26824 (~105KB)
constexpr float SSIM_C1 = 0.0001f;   // 0.01^2
constexpr float SSIM_C2 = 0.0009f;   // 0.03^2
constexpr int MAX_BLOCKS = 16384;
}  // namespace

// Gaussian(sigma=1.5, 11 taps), normalized. Emitted as a constexpr FUNCTION
// (no memory object): every call site has a compile-time k inside a fully
// unrolled loop, so each tap folds to an FFMA immediate operand
// (imm-form rt_SMSP=1 = 2x throughput of 3-reg FFMA). Compiles without
// --expt-relaxed-constexpr because it is explicitly __host__ __device__.
__host__ __device__ __forceinline__ constexpr float gw(int k) {
    switch (k) {
        case 0: case 10: return 0.00102840f;
        case 1: case 9:  return 0.00759876f;
        case 2: case 8:  return 0.03600077f;
        case 3: case 7:  return 0.10936067f;
        case 4: case 6:  return 0.21300555f;
        default:         return 0.26601174f;
    }
}

__device__ float        g_partials[MAX_BLOCKS];
__device__ unsigned int g_ticket;   // zero-init; atomicInc wraps back to 0

// Horizontal 11-tap conv for 4 consecutive outputs, via 4 conflict-free
// LDS.128 loads (lanes cover contiguous 16B chunks). base must be 16B aligned.
__device__ __forceinline__ void hconv4(const float* __restrict__ base, int off4,
                                       float out[4]) {
    const float4* r = reinterpret_cast<const float4*>(base);
    float4 q0 = r[off4 + 0];
    float4 q1 = r[off4 + 1];
    float4 q2 = r[off4 + 2];
    float4 q3 = r[off4 + 3];
    float v[16] = {q0.x, q0.y, q0.z, q0.w, q1.x, q1.y, q1.z, q1.w,
                   q2.x, q2.y, q2.z, q2.w, q3.x, q3.y, q3.z, q3.w};
#pragma unroll
    for (int j = 0; j < 4; j++) {
        float a = 0.f;
#pragma unroll
        for (int k = 0; k < 11; k++) a = fmaf(gw(k), v[j + k], a);
        out[j] = a;
    }
}

__global__ __launch_bounds__(NT, 2)
void ssim_main(const float* __restrict__ pred, const float* __restrict__ targ,
               float* __restrict__ out, double inv_n) {
    extern __shared__ float sm[];
    float* sp   = sm;                      // pred halo
    float* st   = sm + HALO_ELEMS;         // target halo
    float* mids = sm + 2 * HALO_ELEMS;     // 5 buffers of MID_ELEMS (v-conv out)

    const int tid = threadIdx.x;
    const int tx0 = blockIdx.x * TW;
    const int ty0 = blockIdx.y * TH;
    const float* __restrict__ P = pred + (size_t)blockIdx.z * (IMG * IMG);
    const float* __restrict__ T = targ + (size_t)blockIdx.z * (IMG * IMG);

    // ---- Stage A: global -> SMEM halo load (zero pad) --------------------
#pragma unroll 4
    for (int i = tid; i < HALO_ELEMS; i += NT) {
        int sy = i / SWH;
        int sx = i - sy * SWH;
        int gy = ty0 + sy - 5;
        int gx = tx0 + sx - 5;
        float p = 0.f, t = 0.f;
        if ((unsigned)gy < (unsigned)IMG && (unsigned)gx < (unsigned)IMG) {
            p = __ldg(P + gy * IMG + gx);
            t = __ldg(T + gy * IMG + gx);
        }
        sp[i] = p;
        st[i] = t;
    }
    __syncthreads();

    // ---- Stage B: vertical conv of 5 signals, register-blocked -----------
    // products (p^2, t^2, p*t) computed on the fly; 5*VY accumulators.
    constexpr int NSTRIPS = (TH / VY) * SWH;  // 444
    for (int s = tid; s < NSTRIPS; s += NT) {
        int rg  = s / SWH;
        int x   = s - rg * SWH;
        int ry0 = rg * VY;
        float a0[VY], a1[VY], a2[VY], a3[VY], a4[VY];
#pragma unroll
        for (int j = 0; j < VY; j++) a0[j] = a1[j] = a2[j] = a3[j] = a4[j] = 0.f;
#pragma unroll
        for (int r = 0; r < VY + 10; r++) {
            int srow = ry0 + r;
            float p  = sp[srow * SWH + x];
            float t  = st[srow * SWH + x];
            float pp = p * p, tt = t * t, pt = p * t;
#pragma unroll
            for (int j = 0; j < VY; j++) {
                int k = r - j;
                if (k >= 0 && k < 11) {
                    float w = gw(k);
                    a0[j] = fmaf(w, p,  a0[j]);
                    a1[j] = fmaf(w, t,  a1[j]);
                    a2[j] = fmaf(w, pp, a2[j]);
                    a3[j] = fmaf(w, tt, a3[j]);
                    a4[j] = fmaf(w, pt, a4[j]);
                }
            }
        }
#pragma unroll
        for (int j = 0; j < VY; j++) {
            int o = (ry0 + j) * SWM + x;
            mids[0 * MID_ELEMS + o] = a0[j];
            mids[1 * MID_ELEMS + o] = a1[j];
            mids[2 * MID_ELEMS + o] = a2[j];
            mids[3 * MID_ELEMS + o] = a3[j];
            mids[4 * MID_ELEMS + o] = a4[j];
        }
    }
    __syncthreads();

    // ---- Stage C: horizontal conv + SSIM map + accumulate -----------------
    constexpr int GPR = TW / HX;          // 16 groups per row
    constexpr int NGROUPS = TH * GPR;     // 768 = 3 * NT (perfect balance)
    float local = 0.f;
    for (int g = tid; g < NGROUPS; g += NT) {
        int oy   = g / GPR;
        int gx4  = g - oy * GPR;          // float4 offset == output x0/4
        int gy   = ty0 + oy;

        float m1[HX], m2[HX], e0[HX], e1[HX], e2[HX];
        const float* rowbase = mids + oy * SWM;
        hconv4(rowbase + 0 * MID_ELEMS, gx4, m1);
        hconv4(rowbase + 1 * MID_ELEMS, gx4, m2);
        hconv4(rowbase + 2 * MID_ELEMS, gx4, e0);
        hconv4(rowbase + 3 * MID_ELEMS, gx4, e1);
        hconv4(rowbase + 4 * MID_ELEMS, gx4, e2);

        if (gy < IMG) {  // y-tail tile guard (x always full: 512 % 64 == 0)
#pragma unroll
            for (int j = 0; j < HX; j++) {
                float mu1  = m1[j], mu2 = m2[j];
                float mu1s = mu1 * mu1;
                float mu2s = mu2 * mu2;
                float m12  = mu1 * mu2;
                float s1   = e0[j] - mu1s;
                float s2   = e1[j] - mu2s;
                float s12  = e2[j] - m12;
                float num  = (2.f * m12 + SSIM_C1) * (2.f * s12 + SSIM_C2);
                float den  = (mu1s + mu2s + SSIM_C1) * (s1 + s2 + SSIM_C2);
                local += __fdividef(num, den);
            }
        }
    }

    // ---- Block reduction -> per-block partial ----------------------------
#pragma unroll
    for (int o = 16; o > 0; o >>= 1)
        local += __shfl_xor_sync(0xffffffffu, local, o);
    __syncthreads();  // done reading mids; safe to reuse sm
    if ((tid & 31) == 0) sm[tid >> 5] = local;
    __syncthreads();

    const unsigned nblocks =
        gridDim.x * gridDim.y * gridDim.z;
    const unsigned bid =
        blockIdx.x + gridDim.x * (blockIdx.y + gridDim.y * blockIdx.z);

    if (tid == 0) {
        float bs = 0.f;
#pragma unroll
        for (int w = 0; w < NT / 32; w++) bs += sm[w];
        g_partials[bid] = bs;
        __threadfence();
        // atomicInc wraps to 0 when reaching nblocks-1 -> self-resetting.
        unsigned ticket = atomicInc(&g_ticket, nblocks - 1u);
        sm[0] = (ticket == nblocks - 1u) ? 1.f : 0.f;
    }
    __syncthreads();

    // ---- Last block: reduce partials, write scalar ------------------------
    if (sm[0] != 0.f) {
        double acc = 0.0;
        for (unsigned i = tid; i < nblocks; i += NT)
            acc += (double)g_partials[i];
#pragma unroll
        for (int o = 16; o > 0; o >>= 1)
            acc += __shfl_xor_sync(0xffffffffu, acc, o);
        __syncthreads();
        double* dsm = reinterpret_cast<double*>(sm);
        if ((tid & 31) == 0) dsm[tid >> 5] = acc;
        __syncthreads();
        if (tid == 0) {
            double s = 0.0;
#pragma unroll
            for (int w = 0; w < NT / 32; w++) s += dsm[w];
            out[0] = (float)(1.0 - s * inv_n);
        }
    }
}

extern "C" void kernel_launch(void* const* d_in, const int* in_sizes, int n_in,
                              void* d_out, int out_size) {
    const float* pred = (const float*)d_in[0];
    const float* targ = (const float*)d_in[1];
    float* out = (float*)d_out;

    const int total  = in_sizes[0];             // 32*3*512*512
    const int planes = total / (IMG * IMG);     // 96
    const double inv_n = 1.0 / (double)total;

    static bool attr_done = false;
    if (!attr_done) {
        cudaFuncSetAttribute(ssim_main,
                             cudaFuncAttributeMaxDynamicSharedMemorySize,
                             (int)(SMEM_FLOATS * sizeof(float)));
        attr_done = true;
    }

    dim3 grid(IMG / TW, (IMG + TH - 1) / TH, planes);
    ssim_main<<<grid, NT, SMEM_FLOATS * sizeof(float)>>>(pred, targ, out, inv_n);
}

// round 9
// speedup vs baseline: 1.1722x; 1.1722x over previous
#include <cuda_runtime.h>

// ---------------------------------------------------------------------------
// SSIM loss, fully fused single kernel: 5 separable 11x11 Gaussian convs +
// SSIM map + global mean. pred/target: (32,3,512,512) fp32.
// Output: scalar fp32 = 1 - mean(ssim_map).
// Occupancy-optimized: 56.6KB smem/block -> 4 blocks/SM (32 warps).
// ---------------------------------------------------------------------------

namespace {
constexpr int IMG  = 512;
constexpr int TW   = 64;          // output tile width
constexpr int TH   = 24;          // output tile height (small -> 4 blocks/SM)
constexpr int SWH  = TW + 10;     // 74  halo width
constexpr int SHH  = TH + 10;     // 34  halo height
constexpr int SWM  = 76;          // padded mid-row stride (16B aligned)
constexpr int NT   = 256;         // threads per block
constexpr int VY   = 8;           // rows per thread in vertical pass
constexpr int HX   = 4;           // cols per thread in horizontal pass
constexpr int HALO_ELEMS = SHH * SWH;              // 2516
constexpr int MID_ELEMS  = TH * SWM;               // 1824
constexpr int SMEM_FLOATS = 2 * HALO_ELEMS + 5 * MID_ELEMS;  // 14152 (~56.6KB)
constexpr float SSIM_C1 = 0.0001f;   // 0.01^2
constexpr float SSIM_C2 = 0.0009f;   // 0.03^2
constexpr int MAX_BLOCKS = 32768;
}  // namespace

// Gaussian(sigma=1.5, 11 taps), normalized. constexpr FUNCTION (no memory
// object): every call site has a compile-time k inside fully unrolled loops,
// so each tap folds to an FFMA immediate/constant operand. No LDC/LDG.
__host__ __device__ __forceinline__ constexpr float gw(int k) {
    switch (k) {
        case 0: case 10: return 0.00102840f;
        case 1: case 9:  return 0.00759876f;
        case 2: case 8:  return 0.03600077f;
        case 3: case 7:  return 0.10936067f;
        case 4: case 6:  return 0.21300555f;
        default:         return 0.26601174f;
    }
}

__device__ float        g_partials[MAX_BLOCKS];
__device__ unsigned int g_ticket;   // zero-init; atomicInc wraps back to 0

// Horizontal 11-tap conv for 4 consecutive outputs, via 4 conflict-free
// LDS.128 loads (lanes cover contiguous 16B chunks). base must be 16B aligned.
__device__ __forceinline__ void hconv4(const float* __restrict__ base, int off4,
                                       float out[4]) {
    const float4* r = reinterpret_cast<const float4*>(base);
    float4 q0 = r[off4 + 0];
    float4 q1 = r[off4 + 1];
    float4 q2 = r[off4 + 2];
    float4 q3 = r[off4 + 3];
    float v[16] = {q0.x, q0.y, q0.z, q0.w, q1.x, q1.y, q1.z, q1.w,
                   q2.x, q2.y, q2.z, q2.w, q3.x, q3.y, q3.z, q3.w};
#pragma unroll
    for (int j = 0; j < 4; j++) {
        float a = 0.f;
#pragma unroll
        for (int k = 0; k < 11; k++) a = fmaf(gw(k), v[j + k], a);
        out[j] = a;
    }
}

__global__ __launch_bounds__(NT, 4)
void ssim_main(const float* __restrict__ pred, const float* __restrict__ targ,
               float* __restrict__ out, double inv_n) {
    extern __shared__ float sm[];
    float* sp   = sm;                      // pred halo
    float* st   = sm + HALO_ELEMS;         // target halo
    float* mids = sm + 2 * HALO_ELEMS;     // 5 buffers of MID_ELEMS (v-conv out)

    const int tid = threadIdx.x;
    const int tx0 = blockIdx.x * TW;
    const int ty0 = blockIdx.y * TH;
    const float* __restrict__ P = pred + (size_t)blockIdx.z * (IMG * IMG);
    const float* __restrict__ T = targ + (size_t)blockIdx.z * (IMG * IMG);

    // ---- Stage A: global -> SMEM halo load (zero pad) --------------------
#pragma unroll 4
    for (int i = tid; i < HALO_ELEMS; i += NT) {
        int sy = i / SWH;
        int sx = i - sy * SWH;
        int gy = ty0 + sy - 5;
        int gx = tx0 + sx - 5;
        float p = 0.f, t = 0.f;
        if ((unsigned)gy < (unsigned)IMG && (unsigned)gx < (unsigned)IMG) {
            p = __ldg(P + gy * IMG + gx);
            t = __ldg(T + gy * IMG + gx);
        }
        sp[i] = p;
        st[i] = t;
    }
    __syncthreads();

    // ---- Stage B: vertical conv of 5 signals, register-blocked -----------
    // products (p^2, t^2, p*t) computed on the fly; 5*VY accumulators.
    constexpr int NSTRIPS = (TH / VY) * SWH;  // 222 (single pass at NT=256)
    for (int s = tid; s < NSTRIPS; s += NT) {
        int rg  = s / SWH;
        int x   = s - rg * SWH;
        int ry0 = rg * VY;
        float a0[VY], a1[VY], a2[VY], a3[VY], a4[VY];
#pragma unroll
        for (int j = 0; j < VY; j++) a0[j] = a1[j] = a2[j] = a3[j] = a4[j] = 0.f;
#pragma unroll
        for (int r = 0; r < VY + 10; r++) {
            int srow = ry0 + r;
            float p  = sp[srow * SWH + x];
            float t  = st[srow * SWH + x];
            float pp = p * p, tt = t * t, pt = p * t;
#pragma unroll
            for (int j = 0; j < VY; j++) {
                int k = r - j;
                if (k >= 0 && k < 11) {
                    float w = gw(k);
                    a0[j] = fmaf(w, p,  a0[j]);
                    a1[j] = fmaf(w, t,  a1[j]);
                    a2[j] = fmaf(w, pp, a2[j]);
                    a3[j] = fmaf(w, tt, a3[j]);
                    a4[j] = fmaf(w, pt, a4[j]);
                }
            }
        }
#pragma unroll
        for (int j = 0; j < VY; j++) {
            int o = (ry0 + j) * SWM + x;
            mids[0 * MID_ELEMS + o] = a0[j];
            mids[1 * MID_ELEMS + o] = a1[j];
            mids[2 * MID_ELEMS + o] = a2[j];
            mids[3 * MID_ELEMS + o] = a3[j];
            mids[4 * MID_ELEMS + o] = a4[j];
        }
    }
    __syncthreads();

    // ---- Stage C: horizontal conv + SSIM map + accumulate -----------------
    constexpr int GPR = TW / HX;          // 16 groups per row
    constexpr int NGROUPS = TH * GPR;     // 384
    float local = 0.f;
    for (int g = tid; g < NGROUPS; g += NT) {
        int oy   = g / GPR;
        int gx4  = g - oy * GPR;          // float4 offset == output x0/4
        int gy   = ty0 + oy;

        float m1[HX], m2[HX], e0[HX], e1[HX], e2[HX];
        const float* rowbase = mids + oy * SWM;
        hconv4(rowbase + 0 * MID_ELEMS, gx4, m1);
        hconv4(rowbase + 1 * MID_ELEMS, gx4, m2);
        hconv4(rowbase + 2 * MID_ELEMS, gx4, e0);
        hconv4(rowbase + 3 * MID_ELEMS, gx4, e1);
        hconv4(rowbase + 4 * MID_ELEMS, gx4, e2);

        if (gy < IMG) {  // y-tail tile guard (x always full: 512 % 64 == 0)
#pragma unroll
            for (int j = 0; j < HX; j++) {
                float mu1  = m1[j], mu2 = m2[j];
                float mu1s = mu1 * mu1;
                float mu2s = mu2 * mu2;
                float m12  = mu1 * mu2;
                float s1   = e0[j] - mu1s;
                float s2   = e1[j] - mu2s;
                float s12  = e2[j] - m12;
                float num  = (2.f * m12 + SSIM_C1) * (2.f * s12 + SSIM_C2);
                float den  = (mu1s + mu2s + SSIM_C1) * (s1 + s2 + SSIM_C2);
                local += __fdividef(num, den);
            }
        }
    }

    // ---- Block reduction -> per-block partial ----------------------------
#pragma unroll
    for (int o = 16; o > 0; o >>= 1)
        local += __shfl_xor_sync(0xffffffffu, local, o);
    __syncthreads();  // done reading mids; safe to reuse sm
    if ((tid & 31) == 0) sm[tid >> 5] = local;
    __syncthreads();

    const unsigned nblocks =
        gridDim.x * gridDim.y * gridDim.z;
    const unsigned bid =
        blockIdx.x + gridDim.x * (blockIdx.y + gridDim.y * blockIdx.z);

    if (tid == 0) {
        float bs = 0.f;
#pragma unroll
        for (int w = 0; w < NT / 32; w++) bs += sm[w];
        g_partials[bid] = bs;
        __threadfence();
        // atomicInc wraps to 0 when reaching nblocks-1 -> self-resetting.
        unsigned ticket = atomicInc(&g_ticket, nblocks - 1u);
        sm[0] = (ticket == nblocks - 1u) ? 1.f : 0.f;
    }
    __syncthreads();

    // ---- Last block: reduce partials, write scalar ------------------------
    if (sm[0] != 0.f) {
        double acc = 0.0;
        for (unsigned i = tid; i < nblocks; i += NT)
            acc += (double)g_partials[i];
#pragma unroll
        for (int o = 16; o > 0; o >>= 1)
            acc += __shfl_xor_sync(0xffffffffu, acc, o);
        __syncthreads();
        double* dsm = reinterpret_cast<double*>(sm);
        if ((tid & 31) == 0) dsm[tid >> 5] = acc;
        __syncthreads();
        if (tid == 0) {
            double s = 0.0;
#pragma unroll
            for (int w = 0; w < NT / 32; w++) s += dsm[w];
            out[0] = (float)(1.0 - s * inv_n);
        }
    }
}

extern "C" void kernel_launch(void* const* d_in, const int* in_sizes, int n_in,
                              void* d_out, int out_size) {
    const float* pred = (const float*)d_in[0];
    const float* targ = (const float*)d_in[1];
    float* out = (float*)d_out;

    const int total  = in_sizes[0];             // 32*3*512*512
    const int planes = total / (IMG * IMG);     // 96
    const double inv_n = 1.0 / (double)total;

    static bool attr_done = false;
    if (!attr_done) {
        cudaFuncSetAttribute(ssim_main,
                             cudaFuncAttributeMaxDynamicSharedMemorySize,
                             (int)(SMEM_FLOATS * sizeof(float)));
        attr_done = true;
    }

    dim3 grid(IMG / TW, (IMG + TH - 1) / TH, planes);
    ssim_main<<<grid, NT, SMEM_FLOATS * sizeof(float)>>>(pred, targ, out, inv_n);
}